// round 4
// baseline (speedup 1.0000x reference)
#include <cuda_runtime.h>
#include <cstdint>

// Problem constants
#define NB 8
#define NW 32
#define NX 64
#define NY 64
#define NT 40
#define NKZ 8          // retained T modes (M3)
#define NK 24          // retained X/Y modes (2*M1 = 2*M2)
#define XYT 163840     // 64*64*40
#define YTD 2560       // 64*40
#define NMODE 4608     // 24*24*8
#define WPL 4718592    // 4*32*32*12*12*8  (spectral weights per layer)

// ---- scratch (device globals; no allocations anywhere) ----
static __device__ float  g_bufA[(size_t)NB*NW*XYT];                 // 168 MB
static __device__ float  g_bufB[(size_t)NB*NW*XYT];                 // 168 MB
static __device__ float2 g_ft1[(size_t)NB*NW*NX*NY*NKZ];            // 67 MB
static __device__ float2 g_ft2[(size_t)NB*NW*NX*NK*NKZ];            // 25 MB
static __device__ float2 g_modes [(size_t)NB*NW*NMODE];             // 9.4 MB
static __device__ float2 g_modes2[(size_t)NB*NW*NMODE];             // 9.4 MB
static __device__ float2 g_wt[(size_t)3*WPL];                       // 113 MB (transposed spectral weights)
static __device__ float2 g_tw_t[NKZ*NT];    // forward T twiddles  e^{-2pi i k t/40}
static __device__ float2 g_itw_t[NKZ*NT];   // inverse T twiddles  c_k/(XYT) * e^{+2pi i k t/40}
static __device__ float2 g_tw_yx[NK*64];    // forward X/Y twiddles e^{-2pi i kv y/64}

__device__ __forceinline__ void cfma(float2& a, float2 b, float2 c){
  a.x = fmaf(b.x, c.x, fmaf(-b.y, c.y, a.x));
  a.y = fmaf(b.x, c.y, fmaf( b.y, c.x, a.y));
}
__device__ __forceinline__ void cfma_cj(float2& a, float2 b, float2 c){ // a += b*conj(c)
  a.x = fmaf(b.x, c.x, fmaf( b.y, c.y, a.x));
  a.y = fmaf(b.y, c.x, fmaf(-b.x, c.y, a.y));
}
__device__ __forceinline__ float gelu_f(float z){
  return 0.5f*z*(1.0f + erff(z*0.7071067811865476f));
}

// ---- twiddle tables ----
__global__ void k_init_tw(){
  int tid = threadIdx.x;
  for (int i = tid; i < NKZ*NT; i += blockDim.x){
    int k = i / NT, t = i % NT;
    float s, c; sincospif(-(float)(k*t)/20.0f, &s, &c);   // -2pi k t / 40
    g_tw_t[i] = make_float2(c, s);
    float sc = ((k==0) ? 1.0f : 2.0f) * (1.0f/163840.0f);
    float s2, c2; sincospif((float)(k*t)/20.0f, &s2, &c2);
    g_itw_t[i] = make_float2(sc*c2, sc*s2);
  }
  for (int i = tid; i < NK*64; i += blockDim.x){
    int j = i / 64, y = i % 64;
    int kv = (j < 12) ? j : j + 40;                        // 0..11, 52..63
    float s, c; sincospif(-(float)(kv*y)/32.0f, &s, &c);   // -2pi kv y / 64
    g_tw_yx[i] = make_float2(c, s);
  }
}

// ---- transpose spectral weights [r][io][mloc] -> [mode][io] via 32x32 shared tile ----
// in idx = (r*1024 + io)*1152 + mloc, mloc = m1*96 + m2*8 + m3
// mode = r1*2304 + r2*96 + m1*192 + (mloc%96)
__global__ void __launch_bounds__(256) k_prep_w_t(const float* __restrict__ wr,
                                                  const float* __restrict__ wi, int L){
  __shared__ float2 s[32][33];
  int m0  = blockIdx.x * 32;     // 36 tiles over mloc (1152)
  int io0 = blockIdx.y * 32;     // 32 tiles over io (1024)
  int r   = blockIdx.z;
  int tid = threadIdx.x;
  {
    int mt = tid & 31, iot0 = tid >> 5;
    const size_t inbase = (size_t)r * 1024 * 1152;
    #pragma unroll
    for (int u = 0; u < 4; u++){
      int io = io0 + iot0 + u*8;
      size_t off = inbase + (size_t)io*1152 + m0 + mt;
      s[iot0 + u*8][mt] = make_float2(wr[off], wi[off]);
    }
  }
  __syncthreads();
  {
    int iot = tid & 31, mt0 = tid >> 5;
    int rbase = (r & 1) * 2304 + ((r >> 1) & 1) * 96;
    float2* dst = g_wt + (size_t)L*WPL;
    #pragma unroll
    for (int u = 0; u < 4; u++){
      int m  = m0 + mt0 + u*8;
      int m1 = m / 96, rem = m % 96;
      int mode = rbase + m1*192 + rem;
      dst[(size_t)mode*1024 + io0 + iot] = s[iot][mt0 + u*8];
    }
  }
}

// ---- fused fc0 (lift) + forward T-DFT: writes v0 -> bufA and modes -> g_ft1 ----
__global__ void __launch_bounds__(256) k_fc0_fwdT(const float* __restrict__ h,
                      const float* __restrict__ xin,
                      const float* __restrict__ w, const float* __restrict__ b){
  __shared__ float  s_v[2*1280];     // v[hh][c][t]
  __shared__ float  s_in[2][200];    // [t*5+f]
  __shared__ float2 s_tw[NKZ*NT];
  __shared__ float  s_w[160];
  __shared__ float  s_b[32];
  int gx = blockIdx.x, bb = gx >> 11, xy0 = (gx & 2047) * 2;
  int tid = threadIdx.x;
  for (int i = tid; i < 160; i += 256){          // h: 2 x 40t x 2
    int hh = i / 80, r = i % 80;
    s_in[hh][(r >> 1)*5 + (r & 1)] = h[((size_t)(bb*4096 + xy0 + hh)*40)*2 + r];
  }
  for (int i = tid; i < 240; i += 256){          // x: 2 x 40t x 3
    int hh = i / 120, r = i % 120;
    s_in[hh][(r/3)*5 + 2 + (r%3)] = xin[((size_t)(bb*4096 + xy0 + hh)*40)*3 + r];
  }
  if (tid < 160) s_w[tid] = w[tid];
  if (tid < 32)  s_b[tid] = b[tid];
  for (int i = tid; i < NKZ*NT; i += 256) s_tw[i] = g_tw_t[i];
  __syncthreads();
  for (int i = tid; i < 2560; i += 256){
    int hh = i >> 11 ? 1 : (i >= 1280);          // i/1280
    int rem = i - hh*1280;
    int c = rem / 40, t = rem % 40;
    float v = s_b[c];
    #pragma unroll
    for (int f = 0; f < 5; f++) v = fmaf(s_in[hh][t*5 + f], s_w[f*32 + c], v);
    s_v[hh*1280 + c*40 + t] = v;
  }
  __syncthreads();
  // writeback v (coalesced float4)
  size_t base = (size_t)(bb*32)*XYT + (size_t)xy0*NT;
  for (int idx = tid; idx < 640; idx += 256){
    int c = idx / 20, m = idx % 20;
    int hh = m / 10, mm = m % 10;
    float4 v4 = *(const float4*)&s_v[hh*1280 + c*40 + mm*4];
    *(float4*)(g_bufA + base + (size_t)c*XYT + m*4) = v4;
  }
  // forward T modes: 512 outputs (hh,c,k), 2 per thread
  #pragma unroll
  for (int u = 0; u < 2; u++){
    int idx = tid + u*256;
    int hh = idx >> 8, rem = idx & 255, c = rem >> 3, k = rem & 7;
    const float* vp = s_v + hh*1280 + c*40;
    float2 acc = make_float2(0.f, 0.f);
    #pragma unroll 8
    for (int t = 0; t < NT; t++){
      float2 tw = s_tw[k*NT + t];
      acc.x = fmaf(vp[t], tw.x, acc.x);
      acc.y = fmaf(vp[t], tw.y, acc.y);
    }
    g_ft1[(size_t)(bb*32 + c)*32768 + (size_t)(xy0 + hh)*8 + k] = acc;
  }
}

// ---- forward partial DFT over Y: ft1[b,c,x,y,k] -> ft2[b,c,x,j2,k] ----
__global__ void k_fwdY(){
  __shared__ float2 sv[NY*NKZ];     // 4 KB
  __shared__ float2 stw[NK*64];     // 12 KB
  int bcx = blockIdx.x;
  for (int i = threadIdx.x; i < NY*NKZ; i += 192) sv[i] = g_ft1[(size_t)bcx*512 + i];
  for (int i = threadIdx.x; i < NK*64; i += 192) stw[i] = g_tw_yx[i];
  __syncthreads();
  int j = threadIdx.x >> 3, k = threadIdx.x & 7;
  float2 acc = make_float2(0.f, 0.f);
  for (int y = 0; y < 64; y++) cfma(acc, sv[y*8 + k], stw[j*64 + y]);
  g_ft2[(size_t)bcx*192 + threadIdx.x] = acc;
}

// ---- forward partial DFT over X: ft2[b,c,x,j2,k] -> modes[b,c,j1,j2,k] ----
__global__ void k_fwdX(){
  __shared__ float2 stw[64];
  int bc = blockIdx.x / NK, j1 = blockIdx.x % NK;
  if (threadIdx.x < 64) stw[threadIdx.x] = g_tw_yx[j1*64 + threadIdx.x];
  __syncthreads();
  const float2* src = g_ft2 + (size_t)bc*NX*192 + threadIdx.x;
  float2 acc = make_float2(0.f, 0.f);
  for (int x = 0; x < 64; x++) cfma(acc, src[(size_t)x*192], stw[x]);
  g_modes[(size_t)bc*NMODE + j1*192 + threadIdx.x] = acc;
}

// ---- channel mix per mode ----
__global__ void k_mix(int L){
  __shared__ float2 s_in[256];
  __shared__ float2 s_w[1024];
  int m = blockIdx.x;
  int tid = threadIdx.x;
  s_in[tid] = g_modes[(size_t)tid*NMODE + m];
  const float2* wt = g_wt + (size_t)L*WPL + (size_t)m*1024;
  for (int i = tid; i < 1024; i += 256) s_w[i] = wt[i];
  __syncthreads();
  int bb = tid >> 5, o = tid & 31;
  float2 acc = make_float2(0.f, 0.f);
  #pragma unroll 8
  for (int i = 0; i < 32; i++) cfma(acc, s_in[bb*32 + i], s_w[i*32 + o]);
  g_modes2[(size_t)(bb*32 + o)*NMODE + m] = acc;
}

// ---- inverse over X ----
__global__ void k_invX(){
  __shared__ float2 stw[NK*64];     // 12 KB
  int bo = blockIdx.x;
  int tid = threadIdx.x;            // j2*8+k, 192 threads
  for (int i = tid; i < NK*64; i += 192) stw[i] = g_tw_yx[i];
  float2 m[NK];
  #pragma unroll
  for (int j1 = 0; j1 < NK; j1++)
    m[j1] = g_modes2[(size_t)bo*NMODE + j1*192 + tid];
  __syncthreads();
  for (int x = 0; x < 64; x++){
    float2 acc = make_float2(0.f, 0.f);
    #pragma unroll
    for (int j1 = 0; j1 < NK; j1++) cfma_cj(acc, m[j1], stw[j1*64 + x]);
    g_ft2[((size_t)bo*64 + x)*192 + tid] = acc;
  }
}

// ---- inverse over Y ----
__global__ void k_invY(){
  __shared__ float2 s_in[192];
  __shared__ float2 stw[NK*64];
  int box = blockIdx.x;
  if (threadIdx.x < 192) s_in[threadIdx.x] = g_ft2[(size_t)box*192 + threadIdx.x];
  for (int i = threadIdx.x; i < NK*64; i += 256) stw[i] = g_tw_yx[i];
  __syncthreads();
  for (int o = threadIdx.x; o < 512; o += 256){
    int y = o >> 3, k = o & 7;
    float2 acc = make_float2(0.f, 0.f);
    #pragma unroll 8
    for (int j2 = 0; j2 < NK; j2++) cfma_cj(acc, s_in[j2*8 + k], stw[j2*64 + y]);
    g_ft1[(size_t)box*512 + o] = acc;
  }
}

// ---- invT + conv1x1 + gelu + forward T-DFT of the result (next layer's modes) ----
// ft1 slots a block reads are exactly the ones it writes -> block-private, race-free.
__global__ void __launch_bounds__(256) k_invT_pw_fwdT(int dir, const float* __restrict__ convw,
                          const float* __restrict__ convb){
  __shared__ float  s_v[2*1280];
  __shared__ float  s_w[32*33];
  __shared__ float2 s_h[2*32*9];
  __shared__ float2 s_itw[NKZ*NT];
  __shared__ float2 s_twf[NKZ*NT];
  __shared__ float  s_b[NW];
  const float* vin  = dir ? g_bufB : g_bufA;
  float*       vout = dir ? g_bufA : g_bufB;
  int gx  = blockIdx.x;
  int bb  = gx >> 11;
  int xy0 = (gx & 2047) * 2;
  int tid = threadIdx.x;
  size_t base = (size_t)(bb*32)*XYT + (size_t)xy0*NT;

  for (int idx = tid; idx < 640; idx += 256){
    int c = idx / 20, m = idx % 20;
    float4 v4 = *(const float4*)(vin + base + (size_t)c*XYT + m*4);
    int hh = m / 10, mm = m % 10;
    *(float4*)&s_v[hh*1280 + c*40 + mm*4] = v4;
  }
  for (int idx = tid; idx < 512; idx += 256){
    int hh = idx >> 8, rem = idx & 255, o = rem >> 3, k = rem & 7;
    s_h[hh*288 + o*9 + k] = g_ft1[(size_t)(bb*32+o)*32768 + (size_t)(xy0+hh)*8 + k];
  }
  for (int i = tid; i < 1024; i += 256) s_w[(i>>5)*33 + (i&31)] = convw[i];
  for (int i = tid; i < NKZ*NT; i += 256){ s_itw[i] = g_itw_t[i]; s_twf[i] = g_tw_t[i]; }
  if (tid < NW) s_b[tid] = convb[tid];
  __syncthreads();

  int half = tid >> 7, r = tid & 127;
  int o0 = (r >> 3) * 2, t0 = (r & 7) * 5;
  float acc0[5], acc1[5];
  {
    float b0 = s_b[o0], b1 = s_b[o0+1];
    #pragma unroll
    for (int j = 0; j < 5; j++){ acc0[j] = b0; acc1[j] = b1; }
  }
  {
    float2 h0[8], h1[8];
    #pragma unroll
    for (int k = 0; k < 8; k++){
      h0[k] = s_h[half*288 + o0*9 + k];
      h1[k] = s_h[half*288 + (o0+1)*9 + k];
    }
    #pragma unroll
    for (int k = 0; k < 8; k++){
      #pragma unroll
      for (int j = 0; j < 5; j++){
        float2 tw = s_itw[k*NT + t0 + j];
        acc0[j] = fmaf(h0[k].x, tw.x, fmaf(-h0[k].y, tw.y, acc0[j]));
        acc1[j] = fmaf(h1[k].x, tw.x, fmaf(-h1[k].y, tw.y, acc1[j]));
      }
    }
  }
  {
    float w0[32], w1[32];
    #pragma unroll
    for (int i = 0; i < 32; i++){ w0[i] = s_w[o0*33 + i]; w1[i] = s_w[(o0+1)*33 + i]; }
    const float* vh = s_v + half*1280;
    #pragma unroll 8
    for (int i = 0; i < 32; i++){
      float vj[5];
      #pragma unroll
      for (int j = 0; j < 5; j++) vj[j] = vh[i*40 + t0 + j];
      #pragma unroll
      for (int j = 0; j < 5; j++){
        acc0[j] = fmaf(w0[i], vj[j], acc0[j]);
        acc1[j] = fmaf(w1[i], vj[j], acc1[j]);
      }
    }
  }
  #pragma unroll
  for (int j = 0; j < 5; j++){ acc0[j] = gelu_f(acc0[j]); acc1[j] = gelu_f(acc1[j]); }
  __syncthreads();
  {
    float* ov = s_v + half*1280;
    #pragma unroll
    for (int j = 0; j < 5; j++){ ov[o0*40 + t0 + j] = acc0[j]; ov[(o0+1)*40 + t0 + j] = acc1[j]; }
  }
  __syncthreads();
  // writeback v
  for (int idx = tid; idx < 640; idx += 256){
    int c = idx / 20, m = idx % 20;
    int hh = m / 10, mm = m % 10;
    float4 v4 = *(const float4*)&s_v[hh*1280 + c*40 + mm*4];
    *(float4*)(vout + base + (size_t)c*XYT + m*4) = v4;
  }
  // next layer's forward T modes (overwrite our own ft1 slots)
  #pragma unroll
  for (int u = 0; u < 2; u++){
    int idx = tid + u*256;
    int hh = idx >> 8, rem = idx & 255, c = rem >> 3, k = rem & 7;
    const float* vp = s_v + hh*1280 + c*40;
    float2 acc = make_float2(0.f, 0.f);
    #pragma unroll 8
    for (int t = 0; t < NT; t++){
      float2 tw = s_twf[k*NT + t];
      acc.x = fmaf(vp[t], tw.x, acc.x);
      acc.y = fmaf(vp[t], tw.y, acc.y);
    }
    g_ft1[(size_t)(bb*32 + c)*32768 + (size_t)(xy0 + hh)*8 + k] = acc;
  }
}

// ---- last layer: invT + conv1x1 (no act) fused with fc1/gelu/fc2 head ----
__global__ void __launch_bounds__(256) k_invT_head(int dir, const float* __restrict__ convw,
                       const float* __restrict__ convb,
                       const float* __restrict__ w1, const float* __restrict__ b1,
                       const float* __restrict__ w2, const float* __restrict__ b2,
                       float* __restrict__ out){
  __shared__ float  s_v[2*1280];
  __shared__ float  s_w[32*33];
  __shared__ float2 s_h[2*32*9];
  __shared__ float2 s_itw[NKZ*NT];
  __shared__ float  s_b[NW];
  __shared__ float  s_w1[2048];
  __shared__ float  s_b1[64];
  __shared__ float  s_w2[128];
  __shared__ float  s_b2[2];
  __shared__ float  s_red[480];      // [q][p][2]
  const float* vin = dir ? g_bufB : g_bufA;
  int gx  = blockIdx.x;
  int bb  = gx >> 11;
  int xy0 = (gx & 2047) * 2;
  int tid = threadIdx.x;
  size_t base = (size_t)(bb*32)*XYT + (size_t)xy0*NT;

  for (int idx = tid; idx < 640; idx += 256){
    int c = idx / 20, m = idx % 20;
    float4 v4 = *(const float4*)(vin + base + (size_t)c*XYT + m*4);
    int hh = m / 10, mm = m % 10;
    *(float4*)&s_v[hh*1280 + c*40 + mm*4] = v4;
  }
  for (int idx = tid; idx < 512; idx += 256){
    int hh = idx >> 8, rem = idx & 255, o = rem >> 3, k = rem & 7;
    s_h[hh*288 + o*9 + k] = g_ft1[(size_t)(bb*32+o)*32768 + (size_t)(xy0+hh)*8 + k];
  }
  for (int i = tid; i < 1024; i += 256) s_w[(i>>5)*33 + (i&31)] = convw[i];
  for (int i = tid; i < NKZ*NT; i += 256) s_itw[i] = g_itw_t[i];
  if (tid < NW) s_b[tid] = convb[tid];
  for (int i = tid; i < 2048; i += 256) s_w1[i] = w1[i];
  if (tid < 64)  s_b1[tid] = b1[tid];
  if (tid < 128) s_w2[tid] = w2[tid];
  if (tid < 2)   s_b2[tid] = b2[tid];
  __syncthreads();

  int half = tid >> 7, r = tid & 127;
  int o0 = (r >> 3) * 2, t0 = (r & 7) * 5;
  float acc0[5], acc1[5];
  {
    float bb0 = s_b[o0], bb1 = s_b[o0+1];
    #pragma unroll
    for (int j = 0; j < 5; j++){ acc0[j] = bb0; acc1[j] = bb1; }
  }
  {
    float2 h0[8], h1[8];
    #pragma unroll
    for (int k = 0; k < 8; k++){
      h0[k] = s_h[half*288 + o0*9 + k];
      h1[k] = s_h[half*288 + (o0+1)*9 + k];
    }
    #pragma unroll
    for (int k = 0; k < 8; k++){
      #pragma unroll
      for (int j = 0; j < 5; j++){
        float2 tw = s_itw[k*NT + t0 + j];
        acc0[j] = fmaf(h0[k].x, tw.x, fmaf(-h0[k].y, tw.y, acc0[j]));
        acc1[j] = fmaf(h1[k].x, tw.x, fmaf(-h1[k].y, tw.y, acc1[j]));
      }
    }
  }
  {
    float w0[32], wq[32];
    #pragma unroll
    for (int i = 0; i < 32; i++){ w0[i] = s_w[o0*33 + i]; wq[i] = s_w[(o0+1)*33 + i]; }
    const float* vh = s_v + half*1280;
    #pragma unroll 8
    for (int i = 0; i < 32; i++){
      float vj[5];
      #pragma unroll
      for (int j = 0; j < 5; j++) vj[j] = vh[i*40 + t0 + j];
      #pragma unroll
      for (int j = 0; j < 5; j++){
        acc0[j] = fmaf(w0[i], vj[j], acc0[j]);
        acc1[j] = fmaf(wq[i], vj[j], acc1[j]);
      }
    }
  }
  __syncthreads();
  {
    float* ov = s_v + half*1280;
    #pragma unroll
    for (int j = 0; j < 5; j++){ ov[o0*40 + t0 + j] = acc0[j]; ov[(o0+1)*40 + t0 + j] = acc1[j]; }
  }
  __syncthreads();
  // ---- head: 3 threads per point over j-groups ----
  if (tid < 240){
    int p = tid / 3, q = tid - p*3;        // p in 0..79
    int hh = p / 40, t = p % 40;
    const float* vcol = s_v + hh*1280 + t;
    float vr[32];
    #pragma unroll
    for (int c = 0; c < 32; c++) vr[c] = vcol[c*40];
    float p0 = 0.f, p1 = 0.f;
    for (int j = q; j < 64; j += 3){
      float hsum = s_b1[j];
      #pragma unroll 8
      for (int c = 0; c < 32; c++) hsum = fmaf(vr[c], s_w1[c*64 + j], hsum);
      float gj = gelu_f(hsum);
      p0 = fmaf(gj, s_w2[2*j],     p0);
      p1 = fmaf(gj, s_w2[2*j + 1], p1);
    }
    s_red[q*160 + p*2]     = p0;
    s_red[q*160 + p*2 + 1] = p1;
  }
  __syncthreads();
  if (tid < 80){
    int p = tid, hh = p / 40, t = p % 40;
    float o0v = s_b2[0] + s_red[p*2]     + s_red[160 + p*2]     + s_red[320 + p*2];
    float o1v = s_b2[1] + s_red[p*2 + 1] + s_red[160 + p*2 + 1] + s_red[320 + p*2 + 1];
    size_t g = (size_t)bb*4096 + xy0 + hh;
    *(float2*)(out + g*80 + t*2) = make_float2(o0v, o1v);
  }
}

static void run_spectral(int L){
  k_fwdY<<<NB*NW*NX, 192>>>();
  k_fwdX<<<NB*NW*NK, 192>>>();
  k_mix<<<NMODE, 256>>>(L);
  k_invX<<<NB*NW, 192>>>();
  k_invY<<<NB*NW*NX, 256>>>();
}

extern "C" void kernel_launch(void* const* d_in, const int* in_sizes, int n_in,
                              void* d_out, int out_size){
  (void)in_sizes; (void)n_in; (void)out_size;
  const float* h     = (const float*)d_in[0];
  const float* xin   = (const float*)d_in[1];
  const float* fc0_w = (const float*)d_in[2];
  const float* fc0_b = (const float*)d_in[3];
  const float* scr[3] = {(const float*)d_in[4], (const float*)d_in[6], (const float*)d_in[8]};
  const float* sci[3] = {(const float*)d_in[5], (const float*)d_in[7], (const float*)d_in[9]};
  const float* cw[3]  = {(const float*)d_in[10], (const float*)d_in[12], (const float*)d_in[14]};
  const float* cb[3]  = {(const float*)d_in[11], (const float*)d_in[13], (const float*)d_in[15]};
  const float* fc1_w = (const float*)d_in[16];
  const float* fc1_b = (const float*)d_in[17];
  const float* fc2_w = (const float*)d_in[18];
  const float* fc2_b = (const float*)d_in[19];
  float* out = (float*)d_out;

  k_init_tw<<<1, 256>>>();
  dim3 pgrid(36, 32, 4);
  for (int L = 0; L < 3; L++)
    k_prep_w_t<<<pgrid, 256>>>(scr[L], sci[L], L);

  k_fc0_fwdT<<<NB*2048, 256>>>(h, xin, fc0_w, fc0_b);   // v0 -> bufA, modes -> ft1

  run_spectral(0);
  k_invT_pw_fwdT<<<NB*2048, 256>>>(0, cw[0], cb[0]);    // bufA -> bufB (gelu), modes -> ft1

  run_spectral(1);
  k_invT_pw_fwdT<<<NB*2048, 256>>>(1, cw[1], cb[1]);    // bufB -> bufA (gelu), modes -> ft1

  run_spectral(2);
  k_invT_head<<<NB*2048, 256>>>(0, cw[2], cb[2], fc1_w, fc1_b, fc2_w, fc2_b, out);
}